// round 14
// baseline (speedup 1.0000x reference)
#include <cuda_runtime.h>
#include <cuda_fp16.h>
#include <mma.h>
#include <cstdint>
#include <cstddef>

using namespace nvcuda;

#define BB 16
#define CCH 256
#define HH 56
#define WW 56
#define XT_H 58
#define XT_W 66

#define AST 72                            // stage pitch (half elements)
#define STG (256 * AST)                   // one stage (A or B), half elements = 18432
#define SMEM_TOTAL (6 * STG * 2)          // 3 A bufs + 3 B bufs = 221184 B

#define N_GROUPS 224                      // 16 batches * 14 four-row strips (M=256, N=256)
#define N_CTAS 148
#define NTHR 1024

// ---------------- device-global scratch (allocation-free) ----------------
__device__ __half g_xt[BB * XT_H * XT_W * CCH];    // padded channels-last x, fp16 (~31 MB)
__device__ __half g_wt2[9 * CCH * CCH];            // conv0 weights [tap][o][c] fp16
__device__ float g_fsum[BB * CCH];                 // spatial sums of relu(conv)
__device__ float g_c1t[CCH * CCH];                 // center taps, [c][o]
__device__ float g_c2t[CCH * CCH];
__device__ float g_c3t[CCH * CCH];
__device__ float g_c4t[CCH * CCH];
__device__ float g_fc1t[CCH * CCH];
__device__ float g_w1t[CCH * 64];
__device__ float g_w2c[64];

// ---------------- cp.async helpers ----------------
__device__ __forceinline__ void cp16(void* dst_smem, const void* src_gmem) {
    unsigned int d = (unsigned int)__cvta_generic_to_shared(dst_smem);
    asm volatile("cp.async.cg.shared.global [%0], [%1], 16;\n" :: "r"(d), "l"(src_gmem) : "memory");
}
__device__ __forceinline__ void cp_commit() { asm volatile("cp.async.commit_group;\n" ::: "memory"); }
__device__ __forceinline__ void cp_wait0()  { asm volatile("cp.async.wait_group 0;\n" ::: "memory"); }
__device__ __forceinline__ void cp_wait1()  { asm volatile("cp.async.wait_group 1;\n" ::: "memory"); }

// ---------------- init: halo zero + fsum zero + conv0 weight reshape ----------------
__global__ void k_init(const float* __restrict__ w0) {
    int blk = blockIdx.x;
    if (blk < 1384) {                       // halo + fsum zeroing
        int gid = blk * 256 + threadIdx.x;
        if (gid < BB * CCH) g_fsum[gid] = 0.f;
        int n = 16 * 692 * 32;
        if (gid >= n) return;
        int k8 = gid & 31;
        int p  = (gid >> 5) % 692;
        int b  = gid / (692 * 32);
        int row, col;
        if (p < 66)       { row = 0;  col = p; }
        else if (p < 132) { row = 57; col = p - 66; }
        else {
            int q = p - 132;
            row = 1 + q / 10;
            int c10 = q % 10;
            col = (c10 == 0) ? 0 : (56 + c10);
        }
        ((uint4*)g_xt)[(((size_t)b * XT_H + row) * XT_W + col) * 32 + k8] = make_uint4(0, 0, 0, 0);
    } else {                                // conv0 weights -> [tap][o][c] fp16
        int idx = (blk - 1384) * 256 + threadIdx.x;     // 65536
        int c = idx & 255, o = idx >> 8;
        const float* src = w0 + ((size_t)o * 256 + c) * 9;
        float v[9];
#pragma unroll
        for (int t = 0; t < 9; t++) v[t] = src[t];
#pragma unroll
        for (int t = 0; t < 9; t++)
            g_wt2[((size_t)t * 256 + o) * 256 + c] = __float2half(v[t]);
    }
}

// NCHW fp32 -> padded [b][h+1][w+1][c] fp16 (32x32 smem transpose tiles)
__global__ void k_tr(const float* __restrict__ x) {
    __shared__ float tile[32][33];
    int wt = blockIdx.x;                // 0..1
    int h  = blockIdx.y;                // 0..55
    int z  = blockIdx.z;                // b*8 + cblock
    int b = z >> 3, ct = z & 7;
    int tx = threadIdx.x, ty = threadIdx.y;
    int c0 = ct * 32, w0 = wt * 32;
#pragma unroll
    for (int i = 0; i < 4; i++) {
        int c = c0 + ty + i * 8, w = w0 + tx;
        if (w < WW) tile[ty + i * 8][tx] = x[(((size_t)b * CCH + c) * HH + h) * WW + w];
    }
    __syncthreads();
#pragma unroll
    for (int i = 0; i < 4; i++) {
        int w = w0 + ty + i * 8, c = c0 + tx;
        if (w < WW)
            g_xt[(((size_t)b * XT_H + h + 1) * XT_W + (w + 1)) * CCH + c] =
                __float2half(tile[tx][ty + i * 8]);
    }
}

// ---------------- fused conv3x3 + bias + relu + spatial-sum + cent reshape ----------
// M256xN256 per CTA, 1024 threads, 32 warps (8M x 4N grid, 32x64 warp tile)
__global__ void __launch_bounds__(NTHR, 1) k_conv(
        const float* __restrict__ bias0,
        const float* __restrict__ w01, const float* __restrict__ w02,
        const float* __restrict__ w03, const float* __restrict__ w04,
        const float* __restrict__ fc1, const float* __restrict__ w1,
        const float* __restrict__ w2) {
    extern __shared__ __align__(128) __half sm[];
    // buffers: A[k] = sm + k*STG, B[k] = sm + (3+k)*STG

    int tid = threadIdx.x, wid = tid >> 5, lane = tid & 31;
    int warpM = wid >> 2, warpN = wid & 3;        // 8M x 4N
    int m0 = warpM * 32, n0 = warpN * 64;

    // thread-constant staging geometry: 2 A chunks + 2 B chunks per thread
    int a_m[2], a_c8[2];
    const __half* b_src[2];
    unsigned b_soff[2];
#pragma unroll
    for (int k = 0; k < 2; k++) {
        int i = tid + k * NTHR;               // 0..2047 (A chunks)
        a_c8[k] = i & 7;
        a_m[k]  = i >> 3;
        int c8 = i & 7, o = i >> 3;           // B chunks: same decomposition
        b_src[k]  = g_wt2 + (size_t)o * 256 + c8 * 8;
        b_soff[k] = (unsigned)(o * AST + c8 * 8);
    }

    int cta = blockIdx.x;
    int lo = (int)((long)cta * N_GROUPS / N_CTAS);
    int hi = (int)((long)(cta + 1) * N_GROUPS / N_CTAS);

    for (int g = lo; g < hi; g++) {
        int b = g / 14;
        int h0g = (g % 14) * 4;

        // per-item A gmem bases (thread-constant)
        const __half* a_src[2];
        unsigned a_soff[2];
#pragma unroll
        for (int k = 0; k < 2; k++) {
            int r = a_m[k] >> 6, col = a_m[k] & 63;
            a_src[k]  = g_xt + (((size_t)b * XT_H + h0g + r) * XT_W + col) * CCH + a_c8[k] * 8;
            a_soff[k] = (unsigned)(a_m[k] * AST + a_c8[k] * 8);
        }

        auto load_stage = [&](int s) {
            int buf = s % 3;
            int tap = s % 9, cc = s / 9;
            int kh = tap / 3, kw = tap - kh * 3;
            size_t aoff = (size_t)(kh * XT_W + kw) * CCH + cc * 64;
            size_t boff = (size_t)tap * 65536 + cc * 64;
            __half* SA = sm + buf * STG;
            __half* SB = sm + (3 + buf) * STG;
#pragma unroll
            for (int k = 0; k < 2; k++) cp16(SA + a_soff[k], a_src[k] + aoff);
#pragma unroll
            for (int k = 0; k < 2; k++) cp16(SB + b_soff[k], b_src[k] + boff);
            cp_commit();
        };

        wmma::fragment<wmma::accumulator, 16, 16, 16, __half> acc[2][4];
#pragma unroll
        for (int mi = 0; mi < 2; mi++)
#pragma unroll
            for (int nf = 0; nf < 4; nf++) wmma::fill_fragment(acc[mi][nf], __float2half(0.f));

        load_stage(0);
        load_stage(1);

        for (int s = 0; s < 36; s++) {
            // 1) my stage-s group retired (one group per load_stage, stage order)
            if (s < 34) cp_wait1(); else cp_wait0();
            // 2) barrier: stage-s writes visible to all; stage-(s-1) reads all retired
            __syncthreads();
            // 3) prefetch stage s+2 (overwrites buf (s-1)%3 — safe per barrier)
            if (s + 2 < 36) load_stage(s + 2);

            // 4) MMA on stage s
            __half* As = sm + (s % 3) * STG;
            __half* Bs = sm + (3 + s % 3) * STG;
#pragma unroll
            for (int k16 = 0; k16 < 4; k16++) {
                wmma::fragment<wmma::matrix_a, 16, 16, 16, __half, wmma::row_major> a[2];
#pragma unroll
                for (int mi = 0; mi < 2; mi++)
                    wmma::load_matrix_sync(a[mi], As + (m0 + mi * 16) * AST + k16 * 16, AST);
#pragma unroll
                for (int nf = 0; nf < 4; nf++) {
                    wmma::fragment<wmma::matrix_b, 16, 16, 16, __half, wmma::col_major> bfr;
                    wmma::load_matrix_sync(bfr, Bs + (n0 + nf * 16) * AST + k16 * 16, AST);
#pragma unroll
                    for (int mi = 0; mi < 2; mi++)
                        wmma::mma_sync(acc[mi][nf], a[mi], bfr, acc[mi][nf]);
                }
            }
        }

        // epilogue: scratch aliases A buf0/buf1 region — provably quiescent:
        // every warp is past the s=35 barrier, so only buf2 (stage 35) is being read.
        __half* scr = sm + wid * 256;         // 32 warps x 256 halves = 16 KB < buf0
        int ocol = lane & 15;
#pragma unroll
        for (int nf = 0; nf < 4; nf++) {
            int o = n0 + nf * 16 + ocol;
            float bo = bias0[o];
            float csum = 0.f;
#pragma unroll
            for (int mi = 0; mi < 2; mi++) {
                wmma::store_matrix_sync(scr, acc[mi][nf], 16, wmma::mem_row_major);
                __syncwarp();
                if (lane < 16) {
                    int mbase = (m0 + mi * 16) & 63;          // image col base of this frag
                    int rmax = (mbase == 48) ? 8 : 16;        // cols >= 56 invalid
                    for (int r = 0; r < rmax; r++)
                        csum += fmaxf(__half2float(scr[r * 16 + ocol]) + bo, 0.f);
                }
                __syncwarp();
            }
            if (lane < 16) atomicAdd(&g_fsum[b * 256 + o], csum);
        }
        __syncthreads();     // buf reads/writes quiesced before next item's staging
    }

    // ---- cent reshape slice (hidden in straggler window; leaves matrices L2-hot) ----
    int t0 = (int)((long)cta * 65536 / N_CTAS);
    int t1 = (int)((long)(cta + 1) * 65536 / N_CTAS);
    for (int idx = t0 + tid; idx < t1; idx += NTHR) {
        int o = idx & 255, c = idx >> 8;
        g_c1t[c * 256 + o]  = w01[(o * 256 + c) * 9 + 4];
        g_c2t[c * 256 + o]  = w02[(o * 256 + c) * 9 + 4];
        g_c3t[c * 256 + o]  = w03[(o * 256 + c) * 9 + 4];
        g_c4t[c * 256 + o]  = w04[(o * 256 + c) * 9 + 4];
        g_fc1t[c * 256 + o] = fc1[o * 256 + c];
        if (o < 64) g_w1t[c * 64 + o] = w1[(o * 256 + c) * 9 + 4];
        if (idx < 64) g_w2c[idx] = w2[idx * 9 + 4];
    }
}

// ---------------- tail: 1024 threads, 4-way c-split matvecs + CRF ----------------
__global__ void __launch_bounds__(1024) k_tail(
        const float* __restrict__ b0_1, const float* __restrict__ b0_2,
        const float* __restrict__ b0_3, const float* __restrict__ b0_4,
        const float* __restrict__ b1,   const float* __restrict__ b2,
        const float* __restrict__ fc2w, const float* __restrict__ fc2b,
        const float* __restrict__ compat, const float* __restrict__ sw,
        float* __restrict__ out) {
    __shared__ float s_x[256], s_y[256], sp1[4][256], sp2[4][256], s_f3s[64], s_vs, s_red[256];
    int b = blockIdx.x, t = threadIdx.x;
    int q = t >> 8, o = t & 255;
    int c0 = q * 64;

    if (q == 0) s_x[o] = g_fsum[b * 256 + o] * (1.f / 3136.f);   // f1c
    __syncthreads();

    // step 1: f2 (c1t) + vc (fc1t) -> f_c into s_y
    {
        float p1 = 0.f, p2 = 0.f;
#pragma unroll 16
        for (int i = 0; i < 64; i++) {
            float v = s_x[c0 + i];
            p1 += g_c1t[(c0 + i) * 256 + o] * v;
            p2 += g_fc1t[(c0 + i) * 256 + o] * v;
        }
        sp1[q][o] = p1; sp2[q][o] = p2;
    }
    __syncthreads();
    if (q == 0) {
        float a2 = sp1[0][o] + sp1[1][o] + sp1[2][o] + sp1[3][o] + b0_1[o];
        float av = sp2[0][o] + sp2[1][o] + sp2[2][o] + sp2[3][o];
        s_y[o] = (1.f / (1.f + expf(-av))) * fmaxf(a2, 0.f);
    }
    __syncthreads();

    // step 2: f3 (c2t) -> s_x
    {
        float p = 0.f;
#pragma unroll 16
        for (int i = 0; i < 64; i++) p += g_c2t[(c0 + i) * 256 + o] * s_y[c0 + i];
        sp1[q][o] = p;
    }
    __syncthreads();
    if (q == 0) s_x[o] = fmaxf(sp1[0][o] + sp1[1][o] + sp1[2][o] + sp1[3][o] + b0_2[o], 0.f);
    __syncthreads();

    // step 3: f4 (c3t) partials + f3s (w1t) partials, both from f3 (s_x)
    {
        float p = 0.f;
#pragma unroll 16
        for (int i = 0; i < 64; i++) p += g_c3t[(c0 + i) * 256 + o] * s_x[c0 + i];
        sp1[q][o] = p;
        if (o < 64) {
            float pw = 0.f;
#pragma unroll 16
            for (int i = 0; i < 64; i++) pw += g_w1t[(c0 + i) * 64 + o] * s_x[c0 + i];
            sp2[q][o] = pw;
        }
    }
    __syncthreads();
    float f4 = 0.f;
    if (q == 0) f4 = fmaxf(sp1[0][o] + sp1[1][o] + sp1[2][o] + sp1[3][o] + b0_3[o], 0.f);
    if (t < 64) s_f3s[t] = fmaxf(sp2[0][t] + sp2[1][t] + sp2[2][t] + sp2[3][t] + b1[t], 0.f);
    __syncthreads();

    // CRF (scalar)
    if (t == 0) {
        float u = 0.f;
        for (int c = 0; c < 64; c++) u += g_w2c[c] * s_f3s[c];
        u = fmaxf(u + b2[0], 0.f);
        float c00 = compat[0], c01 = compat[1], c10 = compat[2], c11 = compat[3];
        float sw0 = sw[0], sw1 = sw[1];
        float m = fabsf(u);
        float e0 = expf(u - m), e1 = expf(-u - m);
        float q0 = e0 / (e0 + e1), q1 = e1 / (e0 + e1);
        for (int it = 0; it < 5; it++) {
            float m0 = 0.25f * q0 * sw0, m1 = 0.25f * q1 * sw1;
            float p0 = c00 * m0 + c01 * m1;
            float p1 = c10 * m0 + c11 * m1;
            float x0 = u - p0, x1 = -u - p1;
            float mm = fmaxf(x0, x1);
            float f0 = expf(x0 - mm), f1 = expf(x1 - mm);
            float ssum = f0 + f1;
            q0 = f0 / ssum; q1 = f1 / ssum;
        }
        s_vs = q1;
    }
    __syncthreads();

    if (q == 0) s_y[o] = s_vs * f4;                 // f_s
    __syncthreads();

    // step 4: f_r (c4t) + fc2 dot
    {
        float p = 0.f;
#pragma unroll 16
        for (int i = 0; i < 64; i++) p += g_c4t[(c0 + i) * 256 + o] * s_y[c0 + i];
        sp1[q][o] = p;
    }
    __syncthreads();
    if (q == 0) {
        float fr = fmaxf(sp1[0][o] + sp1[1][o] + sp1[2][o] + sp1[3][o] + b0_4[o], 0.f);
        s_red[o] = fc2w[o] * fr;
    }
    __syncthreads();
    for (int s = 128; s > 0; s >>= 1) {
        if (t < s) s_red[t] += s_red[t + s];
        __syncthreads();
    }
    if (t == 0) out[b] = 1.f / (1.f + expf(-(s_red[0] + fc2b[0])));
}

// ---------------- launch ----------------
extern "C" void kernel_launch(void* const* d_in, const int* in_sizes, int n_in,
                              void* d_out, int out_size) {
    const float* x     = (const float*)d_in[0];
    const float* w0_0  = (const float*)d_in[1];
    const float* b0_0  = (const float*)d_in[2];
    const float* w0_1  = (const float*)d_in[3];
    const float* b0_1  = (const float*)d_in[4];
    const float* w0_2  = (const float*)d_in[5];
    const float* b0_2  = (const float*)d_in[6];
    const float* w0_3  = (const float*)d_in[7];
    const float* b0_3  = (const float*)d_in[8];
    const float* w0_4  = (const float*)d_in[9];
    const float* b0_4  = (const float*)d_in[10];
    const float* w1    = (const float*)d_in[11];
    const float* b1    = (const float*)d_in[12];
    const float* w2    = (const float*)d_in[13];
    const float* b2    = (const float*)d_in[14];
    const float* fc1w  = (const float*)d_in[15];
    const float* fc2w  = (const float*)d_in[16];
    const float* fc2b  = (const float*)d_in[17];
    const float* compat= (const float*)d_in[18];
    const float* sw    = (const float*)d_in[19];
    float* out = (float*)d_out;

    cudaFuncSetAttribute(k_conv, cudaFuncAttributeMaxDynamicSharedMemorySize, SMEM_TOTAL);

    k_init<<<1640, 256>>>(w0_0);
    k_tr<<<dim3(2, 56, 128), dim3(32, 8)>>>(x);
    k_conv<<<N_CTAS, NTHR, SMEM_TOTAL>>>(b0_0, w0_1, w0_2, w0_3, w0_4, fc1w, w1, w2);
    k_tail<<<16, 1024>>>(b0_1, b0_2, b0_3, b0_4, b1, b2, fc2w, fc2b, compat, sw, out);
}

// round 16
// speedup vs baseline: 1.0595x; 1.0595x over previous
#include <cuda_runtime.h>
#include <cuda_fp16.h>
#include <mma.h>
#include <cstdint>
#include <cstddef>

using namespace nvcuda;

#define BB 16
#define CCH 256
#define HH 56
#define WW 56
#define XT_H 58
#define XT_W 66

#define AST 72                            // stage pitch (half elements)
#define STG (256 * AST)                   // one stage (A or B), half elements = 18432
#define SCR_HALVES (16 * 256)             // 16 warps x 16x16 scratch
#define SMEM_TOTAL ((6 * STG + SCR_HALVES) * 2)   // 229376 B

#define N_GROUPS 224                      // 16 batches * 14 four-row strips (M=256, N=256)
#define N_CTAS 148

// ---------------- device-global scratch (allocation-free) ----------------
__device__ __half g_xt[BB * XT_H * XT_W * CCH];    // padded channels-last x, fp16 (~31 MB)
__device__ __half g_wt2[9 * CCH * CCH];            // conv0 weights [tap][o][c] fp16
__device__ float g_fsum[BB * CCH];                 // spatial sums of relu(conv)
__device__ float g_c1t[CCH * CCH];                 // center taps, [c][o]
__device__ float g_c2t[CCH * CCH];
__device__ float g_c3t[CCH * CCH];
__device__ float g_c4t[CCH * CCH];
__device__ float g_fc1t[CCH * CCH];
__device__ float g_w1t[CCH * 64];
__device__ float g_w2c[64];

// ---------------- cp.async helpers ----------------
__device__ __forceinline__ void cp16(void* dst_smem, const void* src_gmem) {
    unsigned int d = (unsigned int)__cvta_generic_to_shared(dst_smem);
    asm volatile("cp.async.cg.shared.global [%0], [%1], 16;\n" :: "r"(d), "l"(src_gmem) : "memory");
}
__device__ __forceinline__ void cp_commit() { asm volatile("cp.async.commit_group;\n" ::: "memory"); }
__device__ __forceinline__ void cp_wait0()  { asm volatile("cp.async.wait_group 0;\n" ::: "memory"); }
__device__ __forceinline__ void cp_wait1()  { asm volatile("cp.async.wait_group 1;\n" ::: "memory"); }

// ---------------- init: halo zero + fsum zero + conv0 weight reshape ----------------
__global__ void k_init(const float* __restrict__ w0) {
    int blk = blockIdx.x;
    if (blk < 1384) {                       // halo + fsum zeroing
        int gid = blk * 256 + threadIdx.x;
        if (gid < BB * CCH) g_fsum[gid] = 0.f;
        int n = 16 * 692 * 32;
        if (gid >= n) return;
        int k8 = gid & 31;
        int p  = (gid >> 5) % 692;
        int b  = gid / (692 * 32);
        int row, col;
        if (p < 66)       { row = 0;  col = p; }
        else if (p < 132) { row = 57; col = p - 66; }
        else {
            int q = p - 132;
            row = 1 + q / 10;
            int c10 = q % 10;
            col = (c10 == 0) ? 0 : (56 + c10);
        }
        ((uint4*)g_xt)[(((size_t)b * XT_H + row) * XT_W + col) * 32 + k8] = make_uint4(0, 0, 0, 0);
    } else {                                // conv0 weights -> [tap][o][c] fp16
        int idx = (blk - 1384) * 256 + threadIdx.x;     // 65536
        int c = idx & 255, o = idx >> 8;
        const float* src = w0 + ((size_t)o * 256 + c) * 9;
        float v[9];
#pragma unroll
        for (int t = 0; t < 9; t++) v[t] = src[t];
#pragma unroll
        for (int t = 0; t < 9; t++)
            g_wt2[((size_t)t * 256 + o) * 256 + c] = __float2half(v[t]);
    }
}

// NCHW fp32 -> padded [b][h+1][w+1][c] fp16 (32x32 smem transpose tiles)
__global__ void k_tr(const float* __restrict__ x) {
    __shared__ float tile[32][33];
    int wt = blockIdx.x;                // 0..1
    int h  = blockIdx.y;                // 0..55
    int z  = blockIdx.z;                // b*8 + cblock
    int b = z >> 3, ct = z & 7;
    int tx = threadIdx.x, ty = threadIdx.y;
    int c0 = ct * 32, w0 = wt * 32;
#pragma unroll
    for (int i = 0; i < 4; i++) {
        int c = c0 + ty + i * 8, w = w0 + tx;
        if (w < WW) tile[ty + i * 8][tx] = x[(((size_t)b * CCH + c) * HH + h) * WW + w];
    }
    __syncthreads();
#pragma unroll
    for (int i = 0; i < 4; i++) {
        int w = w0 + ty + i * 8, c = c0 + tx;
        if (w < WW)
            g_xt[(((size_t)b * XT_H + h + 1) * XT_W + (w + 1)) * CCH + c] =
                __float2half(tile[tx][ty + i * 8]);
    }
}

// filler so k_conv is the 4th launch (ncu captures launch #4)
__global__ void k_dummy() {}

// ---------------- fused conv3x3 + bias + relu + spatial-sum + cent reshape ----------
// M256xN256 per CTA, 512 threads, 16 warps (4M x 4N grid, 64x64 warp tile)
__global__ void __launch_bounds__(512, 1) k_conv(
        const float* __restrict__ bias0,
        const float* __restrict__ w01, const float* __restrict__ w02,
        const float* __restrict__ w03, const float* __restrict__ w04,
        const float* __restrict__ fc1, const float* __restrict__ w1,
        const float* __restrict__ w2) {
    extern __shared__ __align__(128) __half sm[];
    // buffers: A[k] = sm + k*STG, B[k] = sm + (3+k)*STG; scratch at 6*STG

    int tid = threadIdx.x, wid = tid >> 5, lane = tid & 31;
    int warpM = wid >> 2, warpN = wid & 3;        // 4M x 4N
    int m0 = warpM * 64, n0 = warpN * 64;

    // thread-constant staging geometry: 4 A chunks + 4 B chunks per thread
    int a_m[4], a_c8[4];
    const __half* b_src[4];
    unsigned b_soff[4];
#pragma unroll
    for (int k = 0; k < 4; k++) {
        int i = tid + k * 512;
        a_c8[k] = i & 7;
        a_m[k]  = i >> 3;
        int c8 = i & 7, o = i >> 3;
        b_src[k]  = g_wt2 + (size_t)o * 256 + c8 * 8;
        b_soff[k] = (unsigned)(o * AST + c8 * 8);
    }

    int cta = blockIdx.x;
    int lo = (int)((long)cta * N_GROUPS / N_CTAS);
    int hi = (int)((long)(cta + 1) * N_GROUPS / N_CTAS);

    for (int g = lo; g < hi; g++) {
        int b = g / 14;
        int h0g = (g % 14) * 4;

        // per-item A gmem bases (thread-constant)
        const __half* a_src[4];
        unsigned a_soff[4];
#pragma unroll
        for (int k = 0; k < 4; k++) {
            int r = a_m[k] >> 6, col = a_m[k] & 63;
            a_src[k]  = g_xt + (((size_t)b * XT_H + h0g + r) * XT_W + col) * CCH + a_c8[k] * 8;
            a_soff[k] = (unsigned)(a_m[k] * AST + a_c8[k] * 8);
        }

        // stage loader: s -> (tap, cc); buf passed as compile-time-friendly constant
        auto load_stage = [&](int s, int buf) {
            int tap = s % 9, cc = s / 9;
            int kh = (tap >= 3) + (tap >= 6);
            int kw = tap - 3 * kh;
            size_t aoff = (size_t)(kh * XT_W + kw) * CCH + cc * 64;
            size_t boff = (size_t)tap * 65536 + cc * 64;
            __half* SA = sm + buf * STG;
            __half* SB = sm + (3 + buf) * STG;
#pragma unroll
            for (int k = 0; k < 4; k++) cp16(SA + a_soff[k], a_src[k] + aoff);
#pragma unroll
            for (int k = 0; k < 4; k++) cp16(SB + b_soff[k], b_src[k] + boff);
            cp_commit();
        };

        wmma::fragment<wmma::accumulator, 16, 16, 16, __half> acc[4][4];
#pragma unroll
        for (int mi = 0; mi < 4; mi++)
#pragma unroll
            for (int nf = 0; nf < 4; nf++) wmma::fill_fragment(acc[mi][nf], __float2half(0.f));

        auto compute = [&](const __half* As, const __half* Bs) {
#pragma unroll
            for (int k16 = 0; k16 < 4; k16++) {
                wmma::fragment<wmma::matrix_a, 16, 16, 16, __half, wmma::row_major> a[4];
#pragma unroll
                for (int mi = 0; mi < 4; mi++)
                    wmma::load_matrix_sync(a[mi], As + (m0 + mi * 16) * AST + k16 * 16, AST);
#pragma unroll
                for (int nf = 0; nf < 4; nf++) {
                    wmma::fragment<wmma::matrix_b, 16, 16, 16, __half, wmma::col_major> bfr;
                    wmma::load_matrix_sync(bfr, Bs + (n0 + nf * 16) * AST + k16 * 16, AST);
#pragma unroll
                    for (int mi = 0; mi < 4; mi++)
                        wmma::mma_sync(acc[mi][nf], a[mi], bfr, acc[mi][nf]);
                }
            }
        };

        load_stage(0, 0);
        load_stage(1, 1);

        // pipeline invariant entering stage s: groups {s, s+1} in flight (when they exist).
        // wait_group 1 retires group s; barrier makes its writes visible to all warps and
        // proves all warps finished reading stage s-1 (whose buffer s+2 overwrites).
        for (int st = 0; st < 36; st += 3) {
            cp_wait1();
            __syncthreads();
            if (st + 2 < 36) load_stage(st + 2, 2);
            compute(sm + 0 * STG, sm + 3 * STG);

            cp_wait1();
            __syncthreads();
            if (st + 3 < 36) load_stage(st + 3, 0);
            compute(sm + 1 * STG, sm + 4 * STG);

            if (st < 33) cp_wait1(); else cp_wait0();   // s=35: only group 35 pending
            __syncthreads();
            if (st + 4 < 36) load_stage(st + 4, 1);
            compute(sm + 2 * STG, sm + 5 * STG);
        }

        // epilogue: dedicated per-warp scratch (disjoint from all stage buffers)
        __half* scr = sm + 6 * STG + wid * 256;
        int ocol = lane & 15;
#pragma unroll
        for (int nf = 0; nf < 4; nf++) {
            int o = n0 + nf * 16 + ocol;
            float bo = bias0[o];
            float csum = 0.f;
#pragma unroll
            for (int mi = 0; mi < 4; mi++) {
                wmma::store_matrix_sync(scr, acc[mi][nf], 16, wmma::mem_row_major);
                __syncwarp();
                if (lane < 16) {
                    int rmax = (mi == 3) ? 8 : 16;      // image col = mi*16+r; valid < 56
                    for (int r = 0; r < rmax; r++)
                        csum += fmaxf(__half2float(scr[r * 16 + ocol]) + bo, 0.f);
                }
                __syncwarp();
            }
            if (lane < 16) atomicAdd(&g_fsum[b * 256 + o], csum);
        }
        __syncthreads();     // buf reads/writes quiesced before next item's staging
    }

    // ---- cent reshape slice (hidden in straggler window; leaves matrices L2-hot) ----
    int t0 = (int)((long)cta * 65536 / N_CTAS);
    int t1 = (int)((long)(cta + 1) * 65536 / N_CTAS);
    for (int idx = t0 + tid; idx < t1; idx += 512) {
        int o = idx & 255, c = idx >> 8;
        g_c1t[c * 256 + o]  = w01[(o * 256 + c) * 9 + 4];
        g_c2t[c * 256 + o]  = w02[(o * 256 + c) * 9 + 4];
        g_c3t[c * 256 + o]  = w03[(o * 256 + c) * 9 + 4];
        g_c4t[c * 256 + o]  = w04[(o * 256 + c) * 9 + 4];
        g_fc1t[c * 256 + o] = fc1[o * 256 + c];
        if (o < 64) g_w1t[c * 64 + o] = w1[(o * 256 + c) * 9 + 4];
        if (idx < 64) g_w2c[idx] = w2[idx * 9 + 4];
    }
}

// ---------------- tail: 1024 threads, 4-way c-split matvecs + CRF ----------------
__global__ void __launch_bounds__(1024) k_tail(
        const float* __restrict__ b0_1, const float* __restrict__ b0_2,
        const float* __restrict__ b0_3, const float* __restrict__ b0_4,
        const float* __restrict__ b1,   const float* __restrict__ b2,
        const float* __restrict__ fc2w, const float* __restrict__ fc2b,
        const float* __restrict__ compat, const float* __restrict__ sw,
        float* __restrict__ out) {
    __shared__ float s_x[256], s_y[256], sp1[4][256], sp2[4][256], s_f3s[64], s_vs, s_red[256];
    int b = blockIdx.x, t = threadIdx.x;
    int q = t >> 8, o = t & 255;
    int c0 = q * 64;

    if (q == 0) s_x[o] = g_fsum[b * 256 + o] * (1.f / 3136.f);   // f1c
    __syncthreads();

    // step 1: f2 (c1t) + vc (fc1t) -> f_c into s_y
    {
        float p1 = 0.f, p2 = 0.f;
#pragma unroll 16
        for (int i = 0; i < 64; i++) {
            float v = s_x[c0 + i];
            p1 += g_c1t[(c0 + i) * 256 + o] * v;
            p2 += g_fc1t[(c0 + i) * 256 + o] * v;
        }
        sp1[q][o] = p1; sp2[q][o] = p2;
    }
    __syncthreads();
    if (q == 0) {
        float a2 = sp1[0][o] + sp1[1][o] + sp1[2][o] + sp1[3][o] + b0_1[o];
        float av = sp2[0][o] + sp2[1][o] + sp2[2][o] + sp2[3][o];
        s_y[o] = (1.f / (1.f + expf(-av))) * fmaxf(a2, 0.f);
    }
    __syncthreads();

    // step 2: f3 (c2t) -> s_x
    {
        float p = 0.f;
#pragma unroll 16
        for (int i = 0; i < 64; i++) p += g_c2t[(c0 + i) * 256 + o] * s_y[c0 + i];
        sp1[q][o] = p;
    }
    __syncthreads();
    if (q == 0) s_x[o] = fmaxf(sp1[0][o] + sp1[1][o] + sp1[2][o] + sp1[3][o] + b0_2[o], 0.f);
    __syncthreads();

    // step 3: f4 (c3t) partials + f3s (w1t) partials, both from f3 (s_x)
    {
        float p = 0.f;
#pragma unroll 16
        for (int i = 0; i < 64; i++) p += g_c3t[(c0 + i) * 256 + o] * s_x[c0 + i];
        sp1[q][o] = p;
        if (o < 64) {
            float pw = 0.f;
#pragma unroll 16
            for (int i = 0; i < 64; i++) pw += g_w1t[(c0 + i) * 64 + o] * s_x[c0 + i];
            sp2[q][o] = pw;
        }
    }
    __syncthreads();
    float f4 = 0.f;
    if (q == 0) f4 = fmaxf(sp1[0][o] + sp1[1][o] + sp1[2][o] + sp1[3][o] + b0_3[o], 0.f);
    if (t < 64) s_f3s[t] = fmaxf(sp2[0][t] + sp2[1][t] + sp2[2][t] + sp2[3][t] + b1[t], 0.f);
    __syncthreads();

    // CRF (scalar)
    if (t == 0) {
        float u = 0.f;
        for (int c = 0; c < 64; c++) u += g_w2c[c] * s_f3s[c];
        u = fmaxf(u + b2[0], 0.f);
        float c00 = compat[0], c01 = compat[1], c10 = compat[2], c11 = compat[3];
        float sw0 = sw[0], sw1 = sw[1];
        float m = fabsf(u);
        float e0 = expf(u - m), e1 = expf(-u - m);
        float q0 = e0 / (e0 + e1), q1 = e1 / (e0 + e1);
        for (int it = 0; it < 5; it++) {
            float m0 = 0.25f * q0 * sw0, m1 = 0.25f * q1 * sw1;
            float p0 = c00 * m0 + c01 * m1;
            float p1 = c10 * m0 + c11 * m1;
            float x0 = u - p0, x1 = -u - p1;
            float mm = fmaxf(x0, x1);
            float f0 = expf(x0 - mm), f1 = expf(x1 - mm);
            float ssum = f0 + f1;
            q0 = f0 / ssum; q1 = f1 / ssum;
        }
        s_vs = q1;
    }
    __syncthreads();

    if (q == 0) s_y[o] = s_vs * f4;                 // f_s
    __syncthreads();

    // step 4: f_r (c4t) + fc2 dot
    {
        float p = 0.f;
#pragma unroll 16
        for (int i = 0; i < 64; i++) p += g_c4t[(c0 + i) * 256 + o] * s_y[c0 + i];
        sp1[q][o] = p;
    }
    __syncthreads();
    if (q == 0) {
        float fr = fmaxf(sp1[0][o] + sp1[1][o] + sp1[2][o] + sp1[3][o] + b0_4[o], 0.f);
        s_red[o] = fc2w[o] * fr;
    }
    __syncthreads();
    for (int s = 128; s > 0; s >>= 1) {
        if (t < s) s_red[t] += s_red[t + s];
        __syncthreads();
    }
    if (t == 0) out[b] = 1.f / (1.f + expf(-(s_red[0] + fc2b[0])));
}

// ---------------- launch ----------------
extern "C" void kernel_launch(void* const* d_in, const int* in_sizes, int n_in,
                              void* d_out, int out_size) {
    const float* x     = (const float*)d_in[0];
    const float* w0_0  = (const float*)d_in[1];
    const float* b0_0  = (const float*)d_in[2];
    const float* w0_1  = (const float*)d_in[3];
    const float* b0_1  = (const float*)d_in[4];
    const float* w0_2  = (const float*)d_in[5];
    const float* b0_2  = (const float*)d_in[6];
    const float* w0_3  = (const float*)d_in[7];
    const float* b0_3  = (const float*)d_in[8];
    const float* w0_4  = (const float*)d_in[9];
    const float* b0_4  = (const float*)d_in[10];
    const float* w1    = (const float*)d_in[11];
    const float* b1    = (const float*)d_in[12];
    const float* w2    = (const float*)d_in[13];
    const float* b2    = (const float*)d_in[14];
    const float* fc1w  = (const float*)d_in[15];
    const float* fc2w  = (const float*)d_in[16];
    const float* fc2b  = (const float*)d_in[17];
    const float* compat= (const float*)d_in[18];
    const float* sw    = (const float*)d_in[19];
    float* out = (float*)d_out;

    cudaFuncSetAttribute(k_conv, cudaFuncAttributeMaxDynamicSharedMemorySize, SMEM_TOTAL);

    k_init<<<1640, 256>>>(w0_0);                                   // launch 1
    k_tr<<<dim3(2, 56, 128), dim3(32, 8)>>>(x);                    // launch 2
    k_dummy<<<1, 32>>>();                                          // launch 3
    k_conv<<<N_CTAS, 512, SMEM_TOTAL>>>(b0_0, w0_1, w0_2, w0_3,    // launch 4 (profiled)
                                        w0_4, fc1w, w1, w2);
    k_tail<<<16, 1024>>>(b0_1, b0_2, b0_3, b0_4, b1, b2, fc2w,     // launch 5
                         fc2b, compat, sw, out);
}